// round 14
// baseline (speedup 1.0000x reference)
#include <cuda_runtime.h>
#include <cuda_bf16.h>
#include <cstdint>

#define SEQ  2048
#define DIM  64
#define NBLK 256          // 16 batches x 16 s-chunks of 128 rows; 2 CTAs/SM
#define NT   256

// P[d2][d1] = M[d1][d2] partials per (batch,chunk): 64x64 fp32. 4MB, L2-resident.
__device__ float M_part[NBLK * DIM * DIM];
// Reduced M per batch (P layout [d][dp]): 16 x 4096 fp32 = 256KB.
__device__ float M_final[16 * DIM * DIM];
__device__ unsigned bar_cnt = 0;
__device__ volatile unsigned bar_gen = 0;

// smem tile byte offsets (36KB/CTA). Row stride 144B = 64 bf16 + 16B pad
// (16B-multiple for ldmatrix; 36-word stride -> conflict-free bank walk).
#define T_HI0   0        // Khi   | MThi
#define T_LO0   9216     // Klo   | MTlo
#define T_HI1   18432    // Qhi   | Vhi
#define T_LO1   27648    // Qlo   | Vlo
#define TROW    144

__device__ __forceinline__ uint32_t smem_u32(const void* p){
    uint32_t a;
    asm("{ .reg .u64 t; cvta.to.shared.u64 t, %1; cvt.u32.u64 %0, t; }" : "=r"(a) : "l"(p));
    return a;
}
__device__ __forceinline__ void l2_prefetch(const void* p){
    asm volatile("prefetch.global.L2 [%0];" :: "l"(p));
}
__device__ __forceinline__ uint32_t bf16x2_of(float fo, float fe){
    uint32_t r;
    asm("cvt.rn.bf16x2.f32 %0, %1, %2;" : "=r"(r) : "f"(fo), "f"(fe));
    return r;
}
// split fp32 (fe=even idx, fo=odd idx) -> hi word {bf16(fo),bf16(fe)} + residual word
__device__ __forceinline__ void cvt_pair(float fe, float fo, uint32_t &hi, uint32_t &lo){
    hi = bf16x2_of(fo, fe);
    float he = __uint_as_float(hi << 16);
    float ho = __uint_as_float(hi & 0xffff0000u);
    lo = bf16x2_of(fo - ho, fe - he);
}
__device__ __forceinline__ void mma16816(float* c, const uint32_t* a,
                                         uint32_t b0, uint32_t b1){
    asm("mma.sync.aligned.m16n8k16.row.col.f32.bf16.bf16.f32 "
        "{%0,%1,%2,%3}, {%4,%5,%6,%7}, {%8,%9}, {%0,%1,%2,%3};"
        : "+f"(c[0]), "+f"(c[1]), "+f"(c[2]), "+f"(c[3])
        : "r"(a[0]), "r"(a[1]), "r"(a[2]), "r"(a[3]), "r"(b0), "r"(b1));
}
__device__ __forceinline__ void ldsm4(uint32_t* r, uint32_t addr){
    asm volatile("ldmatrix.sync.aligned.m8n8.x4.shared.b16 {%0,%1,%2,%3}, [%4];"
        : "=r"(r[0]), "=r"(r[1]), "=r"(r[2]), "=r"(r[3]) : "r"(addr));
}
__device__ __forceinline__ void ldsm4t(uint32_t* r, uint32_t addr){
    asm volatile("ldmatrix.sync.aligned.m8n8.x4.trans.shared.b16 {%0,%1,%2,%3}, [%4];"
        : "=r"(r[0]), "=r"(r[1]), "=r"(r[2]), "=r"(r[3]) : "r"(addr));
}
__device__ __forceinline__ void grid_barrier(){
    __threadfence();
    __syncthreads();
    if (threadIdx.x == 0) {
        unsigned gen = bar_gen;
        unsigned arrived = atomicAdd(&bar_cnt, 1);
        if (arrived == gridDim.x - 1) {
            bar_cnt = 0;
            __threadfence();
            bar_gen = gen + 1;
        } else {
            while (bar_gen == gen) { }
        }
    }
    __syncthreads();
    __threadfence();
}

// Stage 16 fp32 (one row-chunk) as bf16 hi+lo into natural-layout tiles.
__device__ __forceinline__ void stage_tile(unsigned char* hiB, unsigned char* loB,
                                           const float4* f, int row, int chunk){
    uint32_t h[8], L[8];
#pragma unroll
    for (int j = 0; j < 4; j++){
        cvt_pair(f[j].x, f[j].y, h[2*j],   L[2*j]);
        cvt_pair(f[j].z, f[j].w, h[2*j+1], L[2*j+1]);
    }
    uint4* dh = (uint4*)(hiB + row * TROW + chunk * 32);
    dh[0] = make_uint4(h[0], h[1], h[2], h[3]);
    dh[1] = make_uint4(h[4], h[5], h[6], h[7]);
    uint4* dl = (uint4*)(loB + row * TROW + chunk * 32);
    dl[0] = make_uint4(L[0], L[1], L[2], L[3]);
    dl[1] = make_uint4(L[4], L[5], L[6], L[7]);
}

// ---------------------------------------------------------------------------
// 256 blocks x 256 threads, 2 CTAs/SM.
// Entry: L2-prefetch this block's entire K/Q/V working set (96KB).
// Phase A: partial K^T Q over 128 s-rows (2 subs of 64); all LDG = L2 hits.
// barrier -> Phase R: reduce 16 partials into M_final; then stage V vt0
//                     (out of barrier-2 critical path).
// barrier -> Phase C: stage MT (L2-hot), 2 v-tiles of MMA, write O.
// ---------------------------------------------------------------------------
__global__ __launch_bounds__(NT, 2)
void fused_attn_hmma4(const float* __restrict__ Q, const float* __restrict__ K,
                      const float* __restrict__ V, float* __restrict__ O)
{
    __shared__ __align__(16) unsigned char sm[36864];
    const uint32_t sb = smem_u32(sm);

    const int t = threadIdx.x, warp = t >> 5, lane = t & 31;
    const int g = lane >> 2, tg = lane & 3;         // mma C/epilogue ids
    const int grp = lane >> 3, li = lane & 7;       // ldmatrix ids
    const int half8 = (grp & 1) << 3;
    const int krow  = ((grp >> 1) << 3) + li;       // trans-ldmatrix stored row
    const int wm = warp & 3, wn = warp >> 2;        // warp tile m0=16wm, n0=32wn
    const int m0 = wm * 16, n0 = wn * 32;
    const int blk = blockIdx.x, b = blk >> 4, c = blk & 15;

    const float* Kc = K + ((size_t)b * SEQ + (size_t)c * 128) * DIM;
    const float* Qc = Q + ((size_t)b * SEQ + (size_t)c * 128) * DIM;
    const float* Vc = V + ((size_t)b * SEQ + (size_t)c * 128) * DIM;

    // ---- L2 prefetch of the whole working set: 3 x 256 lines of 128B ----
    {
        const size_t off = (size_t)t * 32;    // one 128B line per thread per tensor
        l2_prefetch(Kc + off);
        l2_prefetch(Qc + off);
        l2_prefetch(Vc + off);
    }

    const int srow = t >> 2, schunk = t & 3;        // staging coords (64 rows x 4 chunks)

    // ========================== Phase A ====================================
    {
        float acc[4][4];
#pragma unroll
        for (int q = 0; q < 4; q++)
#pragma unroll
            for (int i = 0; i < 4; i++) acc[q][i] = 0.0f;

        // trans-ldmatrix bases (K^T rows m, Q^T rows n; tiles stored [s][d])
        const uint32_t aB  = sb + T_HI0 + krow * TROW + 2 * (m0 + half8);
        const uint32_t bB0 = sb + T_HI1 + krow * TROW + 2 * (n0 + half8);
        const uint32_t bB1 = bB0 + 32;      // +16 cols

        for (int sub = 0; sub < 2; sub++) {
            if (sub) __syncthreads();        // tile consumers of prev sub done
            {
                const float4* pk = (const float4*)(Kc + (size_t)(sub * 64 + srow) * DIM + schunk * 16);
                const float4* pq = (const float4*)(Qc + (size_t)(sub * 64 + srow) * DIM + schunk * 16);
                float4 fK[4], fQ[4];
#pragma unroll
                for (int j = 0; j < 4; j++){ fK[j] = pk[j]; fQ[j] = pq[j]; }
                stage_tile(sm + T_HI0, sm + T_LO0, fK, srow, schunk);
                stage_tile(sm + T_HI1, sm + T_LO1, fQ, srow, schunk);
            }
            __syncthreads();

#pragma unroll
            for (int ks = 0; ks < 4; ks++) {
                uint32_t ah[4], al[4], bh[4], bl[4];
                ldsm4t(ah, aB + ks * 2304);
                ldsm4t(al, aB + ks * 2304 + 9216);
                ldsm4t(bh, bB0 + ks * 2304);
                ldsm4t(bl, bB0 + ks * 2304 + 9216);
                mma16816(acc[0], ah, bh[0], bh[2]);
                mma16816(acc[0], ah, bl[0], bl[2]);
                mma16816(acc[0], al, bh[0], bh[2]);
                mma16816(acc[1], ah, bh[1], bh[3]);
                mma16816(acc[1], ah, bl[1], bl[3]);
                mma16816(acc[1], al, bh[1], bh[3]);
                ldsm4t(bh, bB1 + ks * 2304);
                ldsm4t(bl, bB1 + ks * 2304 + 9216);
                mma16816(acc[2], ah, bh[0], bh[2]);
                mma16816(acc[2], ah, bl[0], bl[2]);
                mma16816(acc[2], al, bh[0], bh[2]);
                mma16816(acc[3], ah, bh[1], bh[3]);
                mma16816(acc[3], ah, bl[1], bl[3]);
                mma16816(acc[3], al, bh[1], bh[3]);
            }
        }

        // Epilogue: C[m=d1][n=d2] -> P[d2][d1] partial
        float* Pb = M_part + (size_t)blk * 4096;
#pragma unroll
        for (int q = 0; q < 4; q++) {
            int d2 = n0 + q * 8 + tg * 2;
            int d1 = m0 + g;
            Pb[d2 * 64 + d1]           = acc[q][0];
            Pb[(d2 + 1) * 64 + d1]     = acc[q][1];
            Pb[d2 * 64 + d1 + 8]       = acc[q][2];
            Pb[(d2 + 1) * 64 + d1 + 8] = acc[q][3];
        }
    }

    grid_barrier();     // all partials visible; all Q-tile readers done

    // ============ Phase R: reduce 16 chunk partials -> M_final =============
    {
        const float* src = M_part + (size_t)(b * 16) * 4096 + c * 256 + t;
        float s = 0.0f;
#pragma unroll
        for (int chk = 0; chk < 16; chk++) s += src[(size_t)chk * 4096];
        M_final[b * 4096 + c * 256 + t] = s;
    }

    // Stage V vt0 now (L2 hit; smem Q region free after barrier 1) so it's
    // off the barrier-2 critical path. barrier-2's syncthreads orders it
    // before the vt0 ldsm reads.
    {
        const float4* pv = (const float4*)(Vc + (size_t)srow * DIM + schunk * 16);
        float4 fV[4];
#pragma unroll
        for (int j = 0; j < 4; j++) fV[j] = pv[j];
        stage_tile(sm + T_HI1, sm + T_LO1, fV, srow, schunk);
    }

    grid_barrier();     // M_final visible

    // ========================== Phase C ====================================
    {
        // Stage MT[d][dp] = M_final (P layout [d][dp], L2-hot), split hi/lo.
        {
            const int d = t >> 2, wq = t & 3;
            const float* base = M_final + b * 4096 + d * 64 + wq * 16;
#pragma unroll
            for (int j = 0; j < 8; j++) {
                float2 v = *(const float2*)(base + 2 * j);
                uint32_t hi, lo;
                cvt_pair(v.x, v.y, hi, lo);
                *(uint32_t*)(sm + T_HI0 + d * TROW + (wq * 8 + j) * 4) = hi;
                *(uint32_t*)(sm + T_LO0 + d * TROW + (wq * 8 + j) * 4) = lo;
            }
        }
        __syncthreads();

        // non-trans ldmatrix bases: A = V rows m, B = MT rows n; k along rows
        const uint32_t vB  = sb + T_HI1 + (m0 + half8 + li) * TROW + ((grp >> 1) << 4);
        const uint32_t mB0 = sb + T_HI0 + (n0 + half8 + li) * TROW + ((grp >> 1) << 4);
        const uint32_t mB1 = mB0 + 16 * TROW;

        for (int vt = 0; vt < 2; vt++) {
            float acc2[4][4];
#pragma unroll
            for (int q = 0; q < 4; q++)
#pragma unroll
                for (int i = 0; i < 4; i++) acc2[q][i] = 0.0f;

#pragma unroll
            for (int ks = 0; ks < 4; ks++) {
                uint32_t ah[4], al[4], bh[4], bl[4];
                ldsm4(ah, vB + ks * 32);
                ldsm4(al, vB + ks * 32 + 9216);
                ldsm4(bh, mB0 + ks * 32);
                ldsm4(bl, mB0 + ks * 32 + 9216);
                mma16816(acc2[0], ah, bh[0], bh[2]);
                mma16816(acc2[0], ah, bl[0], bl[2]);
                mma16816(acc2[0], al, bh[0], bh[2]);
                mma16816(acc2[1], ah, bh[1], bh[3]);
                mma16816(acc2[1], ah, bl[1], bl[3]);
                mma16816(acc2[1], al, bh[1], bh[3]);
                ldsm4(bh, mB1 + ks * 32);
                ldsm4(bl, mB1 + ks * 32 + 9216);
                mma16816(acc2[2], ah, bh[0], bh[2]);
                mma16816(acc2[2], ah, bl[0], bl[2]);
                mma16816(acc2[2], al, bh[0], bh[2]);
                mma16816(acc2[3], ah, bh[1], bh[3]);
                mma16816(acc2[3], ah, bl[1], bl[3]);
                mma16816(acc2[3], al, bh[1], bh[3]);
            }

            // Write O rows c*128 + vt*64 + m0 + g (+8), cols n0 + q*8 + 2tg
            float* Ob = O + ((size_t)b * SEQ + (size_t)c * 128 + vt * 64 + m0) * DIM;
#pragma unroll
            for (int q = 0; q < 4; q++) {
                int col = n0 + q * 8 + tg * 2;
                *(float2*)(Ob + (size_t)g * DIM + col) =
                    make_float2(acc2[q][0], acc2[q][1]);
                *(float2*)(Ob + (size_t)(g + 8) * DIM + col) =
                    make_float2(acc2[q][2], acc2[q][3]);
            }

            if (vt == 0) {
                __syncthreads();             // frag reads of vt0 done
                const float4* pv = (const float4*)(Vc + (size_t)(64 + srow) * DIM + schunk * 16);
                float4 fV[4];
#pragma unroll
                for (int j = 0; j < 4; j++) fV[j] = pv[j];
                stage_tile(sm + T_HI1, sm + T_LO1, fV, srow, schunk);
                __syncthreads();
            }
        }
    }
}

// ---------------------------------------------------------------------------
extern "C" void kernel_launch(void* const* d_in, const int* in_sizes, int n_in,
                              void* d_out, int out_size) {
    const float* Q = (const float*)d_in[0];
    const float* K = (const float*)d_in[1];
    const float* V = (const float*)d_in[2];
    float* O = (float*)d_out;

    fused_attn_hmma4<<<NBLK, NT>>>(Q, K, V, O);
}

// round 15
// speedup vs baseline: 1.6427x; 1.6427x over previous
#include <cuda_runtime.h>
#include <cuda_bf16.h>
#include <cstdint>

#define SEQ  2048
#define DIM  64
#define NBLK 256          // 16 batches x 16 s-chunks of 128 rows; 2 CTAs/SM
#define NT   256

// Double-buffered reduced M per batch, P layout [d2][d1]: 2 x 16 x 4096 fp32.
// Buffer parity = grid-barrier generation & 1 (one barrier per launch).
// Zero-initialized at module load; each launch zeroes the OTHER buffer for
// the next launch (stream-ordered => race-free).
__device__ float M_final[2][16 * DIM * DIM];
__device__ unsigned bar_cnt = 0;
__device__ volatile unsigned bar_gen = 0;

// smem tile byte offsets (36KB/CTA). Row stride 144B = 64 bf16 + 16B pad
// (16B-multiple for ldmatrix; 36-word stride -> conflict-free bank walk).
#define T_HI0   0        // Khi   | MThi
#define T_LO0   9216     // Klo   | MTlo
#define T_HI1   18432    // Qhi   | Vhi
#define T_LO1   27648    // Qlo   | Vlo
#define TROW    144

__device__ __forceinline__ uint32_t smem_u32(const void* p){
    uint32_t a;
    asm("{ .reg .u64 t; cvta.to.shared.u64 t, %1; cvt.u32.u64 %0, t; }" : "=r"(a) : "l"(p));
    return a;
}
__device__ __forceinline__ uint32_t bf16x2_of(float fo, float fe){
    uint32_t r;
    asm("cvt.rn.bf16x2.f32 %0, %1, %2;" : "=r"(r) : "f"(fo), "f"(fe));
    return r;
}
// split fp32 (fe=even idx, fo=odd idx) -> hi word {bf16(fo),bf16(fe)} + residual word
__device__ __forceinline__ void cvt_pair(float fe, float fo, uint32_t &hi, uint32_t &lo){
    hi = bf16x2_of(fo, fe);
    float he = __uint_as_float(hi << 16);
    float ho = __uint_as_float(hi & 0xffff0000u);
    lo = bf16x2_of(fo - ho, fe - he);
}
__device__ __forceinline__ void mma16816(float* c, const uint32_t* a,
                                         uint32_t b0, uint32_t b1){
    asm("mma.sync.aligned.m16n8k16.row.col.f32.bf16.bf16.f32 "
        "{%0,%1,%2,%3}, {%4,%5,%6,%7}, {%8,%9}, {%0,%1,%2,%3};"
        : "+f"(c[0]), "+f"(c[1]), "+f"(c[2]), "+f"(c[3])
        : "r"(a[0]), "r"(a[1]), "r"(a[2]), "r"(a[3]), "r"(b0), "r"(b1));
}
__device__ __forceinline__ void ldsm4(uint32_t* r, uint32_t addr){
    asm volatile("ldmatrix.sync.aligned.m8n8.x4.shared.b16 {%0,%1,%2,%3}, [%4];"
        : "=r"(r[0]), "=r"(r[1]), "=r"(r[2]), "=r"(r[3]) : "r"(addr));
}
__device__ __forceinline__ void ldsm4t(uint32_t* r, uint32_t addr){
    asm volatile("ldmatrix.sync.aligned.m8n8.x4.trans.shared.b16 {%0,%1,%2,%3}, [%4];"
        : "=r"(r[0]), "=r"(r[1]), "=r"(r[2]), "=r"(r[3]) : "r"(addr));
}
__device__ __forceinline__ void grid_barrier(){
    __threadfence();
    __syncthreads();
    if (threadIdx.x == 0) {
        unsigned gen = bar_gen;
        unsigned arrived = atomicAdd(&bar_cnt, 1);
        if (arrived == gridDim.x - 1) {
            bar_cnt = 0;
            __threadfence();
            bar_gen = gen + 1;
        } else {
            while (bar_gen == gen) { }
        }
    }
    __syncthreads();
    __threadfence();
}

// Stage 16 fp32 (one row-chunk) as bf16 hi+lo into natural-layout tiles.
__device__ __forceinline__ void stage_tile(unsigned char* hiB, unsigned char* loB,
                                           const float4* f, int row, int chunk){
    uint32_t h[8], L[8];
#pragma unroll
    for (int j = 0; j < 4; j++){
        cvt_pair(f[j].x, f[j].y, h[2*j],   L[2*j]);
        cvt_pair(f[j].z, f[j].w, h[2*j+1], L[2*j+1]);
    }
    uint4* dh = (uint4*)(hiB + row * TROW + chunk * 32);
    dh[0] = make_uint4(h[0], h[1], h[2], h[3]);
    dh[1] = make_uint4(h[4], h[5], h[6], h[7]);
    uint4* dl = (uint4*)(loB + row * TROW + chunk * 32);
    dl[0] = make_uint4(L[0], L[1], L[2], L[3]);
    dl[1] = make_uint4(L[4], L[5], L[6], L[7]);
}

// ---------------------------------------------------------------------------
// 256 blocks x 256 threads, 2 CTAs/SM. ONE grid barrier.
// Phase A: partial K^T Q over this block's 128 s-rows; epilogue atomicAdd
//          into M_final[p] (p = barrier-gen parity). Zero M_final[1-p] for
//          the next launch. Stage V vt0.
// barrier -> Phase C: stage MT from M_final[p] (L2-hot), 2 v-tiles of MMA.
// ---------------------------------------------------------------------------
__global__ __launch_bounds__(NT, 2)
void fused_attn_hmma5(const float* __restrict__ Q, const float* __restrict__ K,
                      const float* __restrict__ V, float* __restrict__ O)
{
    __shared__ __align__(16) unsigned char sm[36864];
    const uint32_t sb = smem_u32(sm);

    const int t = threadIdx.x, warp = t >> 5, lane = t & 31;
    const int g = lane >> 2, tg = lane & 3;         // mma C/epilogue ids
    const int grp = lane >> 3, li = lane & 7;       // ldmatrix ids
    const int half8 = (grp & 1) << 3;
    const int krow  = ((grp >> 1) << 3) + li;       // trans-ldmatrix stored row
    const int wm = warp & 3, wn = warp >> 2;        // warp tile m0=16wm, n0=32wn
    const int m0 = wm * 16, n0 = wn * 32;
    const int blk = blockIdx.x, b = blk >> 4, c = blk & 15;

    // Buffer parity: consistent across all blocks (bar_gen only increments
    // at the single barrier, which every block reads before reaching).
    const int p = (int)(bar_gen & 1u);

    const float* Kc = K + ((size_t)b * SEQ + (size_t)c * 128) * DIM;
    const float* Qc = Q + ((size_t)b * SEQ + (size_t)c * 128) * DIM;
    const float* Vc = V + ((size_t)b * SEQ + (size_t)c * 128) * DIM;

    const int srow = t >> 2, schunk = t & 3;        // staging coords (64 rows x 4 chunks)

    // ========================== Phase A ====================================
    {
        float acc[4][4];
#pragma unroll
        for (int q = 0; q < 4; q++)
#pragma unroll
            for (int i = 0; i < 4; i++) acc[q][i] = 0.0f;

        // trans-ldmatrix bases (K^T rows m, Q^T rows n; tiles stored [s][d])
        const uint32_t aB  = sb + T_HI0 + krow * TROW + 2 * (m0 + half8);
        const uint32_t bB0 = sb + T_HI1 + krow * TROW + 2 * (n0 + half8);
        const uint32_t bB1 = bB0 + 32;      // +16 cols

        for (int sub = 0; sub < 2; sub++) {
            if (sub) __syncthreads();        // tile consumers of prev sub done
            {
                const float4* pk = (const float4*)(Kc + (size_t)(sub * 64 + srow) * DIM + schunk * 16);
                const float4* pq = (const float4*)(Qc + (size_t)(sub * 64 + srow) * DIM + schunk * 16);
                float4 fK[4], fQ[4];
#pragma unroll
                for (int j = 0; j < 4; j++){ fK[j] = pk[j]; fQ[j] = pq[j]; }
                stage_tile(sm + T_HI0, sm + T_LO0, fK, srow, schunk);
                stage_tile(sm + T_HI1, sm + T_LO1, fQ, srow, schunk);
            }
            __syncthreads();

#pragma unroll
            for (int ks = 0; ks < 4; ks++) {
                uint32_t ah[4], al[4], bh[4], bl[4];
                ldsm4t(ah, aB + ks * 2304);
                ldsm4t(al, aB + ks * 2304 + 9216);
                ldsm4t(bh, bB0 + ks * 2304);
                ldsm4t(bl, bB0 + ks * 2304 + 9216);
                mma16816(acc[0], ah, bh[0], bh[2]);
                mma16816(acc[0], ah, bl[0], bl[2]);
                mma16816(acc[0], al, bh[0], bh[2]);
                mma16816(acc[1], ah, bh[1], bh[3]);
                mma16816(acc[1], ah, bl[1], bl[3]);
                mma16816(acc[1], al, bh[1], bh[3]);
                ldsm4t(bh, bB1 + ks * 2304);
                ldsm4t(bl, bB1 + ks * 2304 + 9216);
                mma16816(acc[2], ah, bh[0], bh[2]);
                mma16816(acc[2], ah, bl[0], bl[2]);
                mma16816(acc[2], al, bh[0], bh[2]);
                mma16816(acc[3], ah, bh[1], bh[3]);
                mma16816(acc[3], ah, bl[1], bl[3]);
                mma16816(acc[3], al, bh[1], bh[3]);
            }
        }

        // Epilogue: C[m=d1][n=d2] -> atomicAdd into M_final[p] at P[d2][d1].
        float* Mf = M_final[p] + (size_t)b * 4096;
#pragma unroll
        for (int q = 0; q < 4; q++) {
            int d2 = n0 + q * 8 + tg * 2;
            int d1 = m0 + g;
            atomicAdd(&Mf[d2 * 64 + d1],           acc[q][0]);
            atomicAdd(&Mf[(d2 + 1) * 64 + d1],     acc[q][1]);
            atomicAdd(&Mf[d2 * 64 + d1 + 8],       acc[q][2]);
            atomicAdd(&Mf[(d2 + 1) * 64 + d1 + 8], acc[q][3]);
        }
    }

    // Zero the OTHER buffer for the next launch (nobody reads it this launch;
    // cross-launch ordering is guaranteed by stream order).
    M_final[1 - p][blk * 256 + t] = 0.0f;

    // Stage V vt0 now (off the barrier critical path; smem Q region is free —
    // all trans-ldmatrix reads of Qhi/Qlo finished before the epilogue).
    __syncthreads();
    {
        const float4* pv = (const float4*)(Vc + (size_t)srow * DIM + schunk * 16);
        float4 fV[4];
#pragma unroll
        for (int j = 0; j < 4; j++) fV[j] = pv[j];
        stage_tile(sm + T_HI1, sm + T_LO1, fV, srow, schunk);
    }

    grid_barrier();     // all atomics into M_final[p] complete & visible

    // ========================== Phase C ====================================
    {
        // Stage MT[d][dp] = M_final[p] (P layout [d2=d][d1=dp], L2-hot).
        {
            const int d = t >> 2, wq = t & 3;
            const float* base = M_final[p] + (size_t)b * 4096 + d * 64 + wq * 16;
#pragma unroll
            for (int j = 0; j < 8; j++) {
                float2 v = *(const float2*)(base + 2 * j);
                uint32_t hi, lo;
                cvt_pair(v.x, v.y, hi, lo);
                *(uint32_t*)(sm + T_HI0 + d * TROW + (wq * 8 + j) * 4) = hi;
                *(uint32_t*)(sm + T_LO0 + d * TROW + (wq * 8 + j) * 4) = lo;
            }
        }
        __syncthreads();

        // non-trans ldmatrix bases: A = V rows m, B = MT rows n; k along rows
        const uint32_t vB  = sb + T_HI1 + (m0 + half8 + li) * TROW + ((grp >> 1) << 4);
        const uint32_t mB0 = sb + T_HI0 + (n0 + half8 + li) * TROW + ((grp >> 1) << 4);
        const uint32_t mB1 = mB0 + 16 * TROW;

        for (int vt = 0; vt < 2; vt++) {
            float acc2[4][4];
#pragma unroll
            for (int q = 0; q < 4; q++)
#pragma unroll
                for (int i = 0; i < 4; i++) acc2[q][i] = 0.0f;

#pragma unroll
            for (int ks = 0; ks < 4; ks++) {
                uint32_t ah[4], al[4], bh[4], bl[4];
                ldsm4(ah, vB + ks * 32);
                ldsm4(al, vB + ks * 32 + 9216);
                ldsm4(bh, mB0 + ks * 32);
                ldsm4(bl, mB0 + ks * 32 + 9216);
                mma16816(acc2[0], ah, bh[0], bh[2]);
                mma16816(acc2[0], ah, bl[0], bl[2]);
                mma16816(acc2[0], al, bh[0], bh[2]);
                mma16816(acc2[1], ah, bh[1], bh[3]);
                mma16816(acc2[1], ah, bl[1], bl[3]);
                mma16816(acc2[1], al, bh[1], bh[3]);
                ldsm4(bh, mB1 + ks * 32);
                ldsm4(bl, mB1 + ks * 32 + 9216);
                mma16816(acc2[2], ah, bh[0], bh[2]);
                mma16816(acc2[2], ah, bl[0], bl[2]);
                mma16816(acc2[2], al, bh[0], bh[2]);
                mma16816(acc2[3], ah, bh[1], bh[3]);
                mma16816(acc2[3], ah, bl[1], bl[3]);
                mma16816(acc2[3], al, bh[1], bh[3]);
            }

            // Write O rows c*128 + vt*64 + m0 + g (+8), cols n0 + q*8 + 2tg
            float* Ob = O + ((size_t)b * SEQ + (size_t)c * 128 + vt * 64 + m0) * DIM;
#pragma unroll
            for (int q = 0; q < 4; q++) {
                int col = n0 + q * 8 + tg * 2;
                *(float2*)(Ob + (size_t)g * DIM + col) =
                    make_float2(acc2[q][0], acc2[q][1]);
                *(float2*)(Ob + (size_t)(g + 8) * DIM + col) =
                    make_float2(acc2[q][2], acc2[q][3]);
            }

            if (vt == 0) {
                __syncthreads();             // frag reads of vt0 done
                const float4* pv = (const float4*)(Vc + (size_t)(64 + srow) * DIM + schunk * 16);
                float4 fV[4];
#pragma unroll
                for (int j = 0; j < 4; j++) fV[j] = pv[j];
                stage_tile(sm + T_HI1, sm + T_LO1, fV, srow, schunk);
                __syncthreads();
            }
        }
    }
}

// ---------------------------------------------------------------------------
extern "C" void kernel_launch(void* const* d_in, const int* in_sizes, int n_in,
                              void* d_out, int out_size) {
    const float* Q = (const float*)d_in[0];
    const float* K = (const float*)d_in[1];
    const float* V = (const float*)d_in[2];
    float* O = (float*)d_out;

    fused_attn_hmma5<<<NBLK, NT>>>(Q, K, V, O);
}